// round 9
// baseline (speedup 1.0000x reference)
#include <cuda_runtime.h>

// Problem shape (fixed by the dataset): B=4, S=4096, D=2048, W=4
#define BV 4
#define SV 4096
#define DV 2048
#define TOK 32            // tokens per score block
#define NROWS (TOK + 3)   // 35 real rows (3-row causal halo)
#define NGRP 9            // 36 rows incl 1 pad, 4 rows/group
#define RSLOT 12          // ring slots (12 x 8KB = 96KB dynamic smem)
#define NW 16             // warps per block (512 threads)

// Scratch (no allocations allowed) ------------------------------------------
__device__ int g_mask[BV * SV];
__device__ int g_src [BV * SV];

// Packed f32x2 helpers --------------------------------------------------------
typedef unsigned long long u64;
static __device__ __forceinline__ u64 pk(float lo, float hi) {
    u64 r; asm("mov.b64 %0,{%1,%2};" : "=l"(r) : "f"(lo), "f"(hi)); return r;
}
static __device__ __forceinline__ void upk(u64 v, float& lo, float& hi) {
    asm("mov.b64 {%0,%1},%2;" : "=f"(lo), "=f"(hi) : "l"(v));
}
static __device__ __forceinline__ u64 f2fma(u64 a, u64 b, u64 c) {
    u64 d; asm("fma.rn.f32x2 %0,%1,%2,%3;" : "=l"(d) : "l"(a), "l"(b), "l"(c)); return d;
}
static __device__ __forceinline__ u64 f2mul(u64 a, u64 b) {
    u64 d; asm("mul.rn.f32x2 %0,%1,%2;" : "=l"(d) : "l"(a), "l"(b)); return d;
}

// Warp sum via butterfly shuffle (redux.f32 does NOT exist on sm_103) --------
static __device__ __forceinline__ float warp_sum(float v) {
#pragma unroll
    for (int o = 16; o > 0; o >>= 1)
        v += __shfl_xor_sync(0xffffffffu, v, o);
    return v;
}

// cp.async helpers ------------------------------------------------------------
static __device__ __forceinline__ void cpa16(unsigned dst, const void* src) {
    asm volatile("cp.async.ca.shared.global [%0], [%1], 16;"
                 :: "r"(dst), "l"(src));
}
static __device__ __forceinline__ void cpa_commit() {
    asm volatile("cp.async.commit_group;");
}
template <int N>
static __device__ __forceinline__ void cpa_wait() {
    asm volatile("cp.async.wait_group %0;" :: "n"(N));
}
static __device__ __forceinline__ void sts_zero16(unsigned dst) {
    asm volatile("st.shared.v4.b32 [%0],{%1,%1,%1,%1};" :: "r"(dst), "r"(0));
}

// Sum of 4 silu-gated terms with ONE reciprocal
static __device__ __forceinline__ float silu4(
    float v0, float v1, float v2, float v3,
    float g0, float g1, float g2, float g3)
{
    float d0 = 1.f + __expf(-v0);
    float d1 = 1.f + __expf(-v1);
    float d2 = 1.f + __expf(-v2);
    float d3 = 1.f + __expf(-v3);
    float a0 = g0 * v0, a1 = g1 * v1, a2 = g2 * v2, a3 = g3 * v3;
    float n01 = fmaf(a0, d1, a1 * d0);
    float n23 = fmaf(a2, d3, a3 * d2);
    float D01 = d0 * d1;
    float D23 = d2 * d3;
    float n = fmaf(n01, D23, n23 * D01);
    float D = D01 * D23;
    return __fdividef(n, D);
}

// K1: fused rmsnorm + causal dwconv(W=4) + silu + (p1-p0) dot -> sign/token.
// 512 threads, 4 ch/thread, 32 tokens/block (grid=512 -> 2 blocks/SM, 32
// warps resident via the 64-reg cap). Rows stream through a 12-slot cp.async
// ring; groups of 4 rows with ONE barrier per group.
__global__ void __launch_bounds__(512, 2) score_kernel(
    const float* __restrict__ x, const float* __restrict__ nw,
    const float* __restrict__ cw, const float* __restrict__ pw)
{
    extern __shared__ float4 ring[];     // [RSLOT][512] : 12 x 8KB
    __shared__ float wpart[2][4][NW];    // rinv warp partials (group parity)
    __shared__ float spart[TOK][NW];     // per-token score warp partials

    const int b    = blockIdx.y;
    const int s0   = blockIdx.x * TOK;
    const int tid  = threadIdx.x;
    const int lane = tid & 31, wid = tid >> 5;
    const int c0   = tid * 4;

    unsigned ring_u32;
    {
        unsigned long long g;
        asm("cvta.to.shared.u64 %0, %1;" : "=l"(g) : "l"(ring));
        ring_u32 = (unsigned)g + (unsigned)(tid * 16);
    }

    // Constants: fold nw into conv taps -> wnv[tap][c] = cw[c][tap]*nw[c]
    u64 wnv2[4][2];
    float gch[4];
#pragma unroll
    for (int j = 0; j < 2; j++) {
        int d = c0 + 2 * j;
        float n0 = nw[d], n1 = nw[d + 1];
#pragma unroll
        for (int wi = 0; wi < 4; wi++)
            wnv2[wi][j] = pk(cw[d * 4 + wi] * n0, cw[(d + 1) * 4 + wi] * n1);
    }
#pragma unroll
    for (int c = 0; c < 4; c++) gch[c] = pw[DV + c0 + c] - pw[c0 + c];

    u64 acc2[4][2];
#pragma unroll
    for (int s = 0; s < 4; s++) { acc2[s][0] = 0ull; acc2[s][1] = 0ull; }

    const float* xb = x + (size_t)b * SV * DV + c0;

    // Stage rows 4g..4g+3 into the ring; one commit group per row-group.
    auto produce_group = [&](int g) {
        if (g < NGRP) {
#pragma unroll
            for (int k = 0; k < 4; k++) {
                const int i = 4 * g + k;
                const int r = s0 - 3 + i;
                const unsigned dst =
                    ring_u32 + (unsigned)((i % RSLOT) * 8192);
                if (i < NROWS && r >= 0)
                    cpa16(dst, xb + (size_t)r * DV);
                else
                    sts_zero16(dst);
            }
        }
        cpa_commit();   // empty commit keeps wait_group accounting uniform
    };

    produce_group(0);
    produce_group(1);

#pragma unroll 1
    for (int g = 0; g < NGRP; g++) {
        cpa_wait<1>();   // groups 0..g landed (g+1 may be in flight)

        const int par = g & 1;
        // Phase 1: sumsq of each of the 4 rows (read own 16B)
#pragma unroll
        for (int k = 0; k < 4; k++) {
            const float4 a = ring[((4 * g + k) % RSLOT) * 512 + tid];
            float s = a.x * a.x + a.y * a.y + a.z * a.z + a.w * a.w;
            s = warp_sum(s);
            if (lane == 0) wpart[par][k][wid] = s;
        }
        __syncthreads();

        float rinv[4];
#pragma unroll
        for (int k = 0; k < 4; k++) {
            const float4* wp = (const float4*)wpart[par][k];
            float4 t0 = wp[0], t1 = wp[1], t2 = wp[2], t3 = wp[3];
            float tot = ((t0.x + t0.y) + (t0.z + t0.w))
                      + ((t1.x + t1.y) + (t1.z + t1.w))
                      + ((t2.x + t2.y) + (t2.z + t2.w))
                      + ((t3.x + t3.y) + (t3.z + t3.w));
            rinv[k] = rsqrtf(tot * (1.f / DV) + 1e-5f);
        }

        // Phase 2: conv accumulate + token completion (re-read ring rows)
#pragma unroll
        for (int k = 0; k < 4; k++) {
            const int i = 4 * g + k;
            const float4 a = ring[((4 * g + k) % RSLOT) * 512 + tid];
            const u64 ri2 = pk(rinv[k], rinv[k]);
            u64 xr2[2] = { f2mul(ri2, pk(a.x, a.y)),
                           f2mul(ri2, pk(a.z, a.w)) };

#pragma unroll
            for (int jj = 0; jj < 4; jj++) {
                const int slot = (k + 1 + jj) & 3;
                acc2[slot][0] = f2fma(wnv2[3 - jj][0], xr2[0], acc2[slot][0]);
                acc2[slot][1] = f2fma(wnv2[3 - jj][1], xr2[1], acc2[slot][1]);
            }

            if (i >= 3 && i < NROWS) {
                const int slot = (k + 1) & 3;
                float v0, v1, v2, v3;
                upk(acc2[slot][0], v0, v1);
                upk(acc2[slot][1], v2, v3);
                float p = silu4(v0, v1, v2, v3, gch[0], gch[1], gch[2], gch[3]);
                p = warp_sum(p);
                if (lane == 0) spart[i - 3][wid] = p;
            }
            {   // recycle slot
                const int slot = (k + 1) & 3;
                acc2[slot][0] = 0ull; acc2[slot][1] = 0ull;
            }
        }

        produce_group(g + 2);   // after re-reads: safe to overwrite old slots
    }
    __syncthreads();
    if (tid < TOK) {
        const float4* sp = (const float4*)spart[tid];
        float4 t0 = sp[0], t1 = sp[1], t2 = sp[2], t3 = sp[3];
        float t = ((t0.x + t0.y) + (t0.z + t0.w))
                + ((t1.x + t1.y) + (t1.z + t1.w))
                + ((t2.x + t2.y) + (t2.z + t2.w))
                + ((t3.x + t3.y) + (t3.z + t3.w));
        g_mask[b * SV + s0 + tid] = (t > 0.f) ? 1 : 0;
    }
}

// K2: per-batch inclusive scan of masks -> inverse map src[b][c-1] = s -------
__global__ void __launch_bounds__(1024) scan_kernel() {
    const int b   = blockIdx.x;
    const int tid = threadIdx.x;
    for (int j = tid; j < SV; j += 1024) g_src[b * SV + j] = -1;
    __syncthreads();

    int base = tid * 4;
    int m[4], pre[4];
    int sum = 0;
#pragma unroll
    for (int k = 0; k < 4; k++) {
        m[k] = g_mask[b * SV + base + k];
        sum += m[k];
        pre[k] = sum;
    }
    int lane = tid & 31, wid = tid >> 5;
    int v = sum;
#pragma unroll
    for (int o = 1; o < 32; o <<= 1) {
        int t = __shfl_up_sync(0xffffffffu, v, o);
        if (lane >= o) v += t;
    }
    __shared__ int wsum[32];
    if (lane == 31) wsum[wid] = v;
    __syncthreads();
    if (wid == 0) {
        int t = wsum[lane];
#pragma unroll
        for (int o = 1; o < 32; o <<= 1) {
            int u = __shfl_up_sync(0xffffffffu, t, o);
            if (lane >= o) t += u;
        }
        wsum[lane] = t;
    }
    __syncthreads();
    int offset = (wid > 0 ? wsum[wid - 1] : 0) + (v - sum);
#pragma unroll
    for (int k = 0; k < 4; k++) {
        if (m[k]) g_src[b * SV + offset + pre[k] - 1] = base + k;
    }
}

// K3: row-wise gather of x (selected, packed) or zero-fill -------------------
__global__ void __launch_bounds__(256) scatter_kernel(
    const float* __restrict__ x, float* __restrict__ out)
{
    const int row = blockIdx.x;              // 0 .. B*S-1
    const int b   = row >> 12;               // S = 4096
    const int s   = g_src[row];
    float4* o = (float4*)(out + (size_t)row * DV) + threadIdx.x;
    if (s >= 0) {
        const float4* xr =
            (const float4*)(x + ((size_t)(b << 12) + s) * DV) + threadIdx.x;
        float4 v0 = __ldcs(xr);
        float4 v1 = __ldcs(xr + 256);
        __stcs(o, v0);
        __stcs(o + 256, v1);
    } else {
        float4 z = make_float4(0.f, 0.f, 0.f, 0.f);
        __stcs(o, z);
        __stcs(o + 256, z);
    }
}

extern "C" void kernel_launch(void* const* d_in, const int* in_sizes, int n_in,
                              void* d_out, int out_size) {
    const float* x  = (const float*)d_in[0];  // [B,S,D]
    const float* nw = (const float*)d_in[1];  // [D]
    const float* cw = (const float*)d_in[2];  // [D,4]
    const float* pw = (const float*)d_in[3];  // [2,D]
    float* out = (float*)d_out;               // [B,S,D]

    const int ring_bytes = RSLOT * 8192;      // 96KB dynamic smem
    cudaFuncSetAttribute(score_kernel,
                         cudaFuncAttributeMaxDynamicSharedMemorySize,
                         ring_bytes);
    cudaFuncSetAttribute(score_kernel,
                         cudaFuncAttributePreferredSharedMemoryCarveout, 100);

    dim3 g1(SV / TOK, BV);
    score_kernel<<<g1, 512, ring_bytes>>>(x, nw, cw, pw);
    scan_kernel<<<BV, 1024>>>();
    scatter_kernel<<<BV * SV, 256>>>(x, out);
}

// round 10
// speedup vs baseline: 1.1377x; 1.1377x over previous
#include <cuda_runtime.h>

// Problem shape (fixed by the dataset): B=4, S=4096, D=2048, W=4
#define BV 4
#define SV 4096
#define DV 2048
#define TOK 64            // tokens per score block
#define NROWS 67          // real rows (3-row causal halo)
#define NCHUNK 9          // 72 rows incl 5 pad, 8 rows/chunk
#define RSLOT 12          // ring slots (12 x 8KB = 96KB dynamic smem)

// Scratch (no allocations allowed) ------------------------------------------
__device__ int g_mask[BV * SV];
__device__ int g_src [BV * SV];

// Packed f32x2 helpers --------------------------------------------------------
typedef unsigned long long u64;
static __device__ __forceinline__ u64 pk(float lo, float hi) {
    u64 r; asm("mov.b64 %0,{%1,%2};" : "=l"(r) : "f"(lo), "f"(hi)); return r;
}
static __device__ __forceinline__ void upk(u64 v, float& lo, float& hi) {
    asm("mov.b64 {%0,%1},%2;" : "=f"(lo), "=f"(hi) : "l"(v));
}
static __device__ __forceinline__ u64 f2fma(u64 a, u64 b, u64 c) {
    u64 d; asm("fma.rn.f32x2 %0,%1,%2,%3;" : "=l"(d) : "l"(a), "l"(b), "l"(c)); return d;
}
static __device__ __forceinline__ u64 f2mul(u64 a, u64 b) {
    u64 d; asm("mul.rn.f32x2 %0,%1,%2;" : "=l"(d) : "l"(a), "l"(b)); return d;
}

static __device__ __forceinline__ float warp_sum(float v) {
#pragma unroll
    for (int o = 16; o > 0; o >>= 1)
        v += __shfl_xor_sync(0xffffffffu, v, o);
    return v;
}

// cp.async helpers ------------------------------------------------------------
static __device__ __forceinline__ void cpa16(unsigned dst, const void* src) {
    asm volatile("cp.async.ca.shared.global [%0], [%1], 16;"
                 :: "r"(dst), "l"(src));
}
static __device__ __forceinline__ void cpa_commit() {
    asm volatile("cp.async.commit_group;");
}
template <int N>
static __device__ __forceinline__ void cpa_wait() {
    asm volatile("cp.async.wait_group %0;" :: "n"(N));
}
static __device__ __forceinline__ void sts_zero16(unsigned dst) {
    asm volatile("st.shared.v4.b32 [%0],{%1,%1,%1,%1};" :: "r"(dst), "r"(0));
}

// Sum of 4 silu-gated terms with ONE reciprocal
static __device__ __forceinline__ float silu4(
    float v0, float v1, float v2, float v3,
    float g0, float g1, float g2, float g3)
{
    float d0 = 1.f + __expf(-v0);
    float d1 = 1.f + __expf(-v1);
    float d2 = 1.f + __expf(-v2);
    float d3 = 1.f + __expf(-v3);
    float a0 = g0 * v0, a1 = g1 * v1, a2 = g2 * v2, a3 = g3 * v3;
    float n01 = fmaf(a0, d1, a1 * d0);
    float n23 = fmaf(a2, d3, a3 * d2);
    float D01 = d0 * d1;
    float D23 = d2 * d3;
    float n = fmaf(n01, D23, n23 * D01);
    float D = D01 * D23;
    return __fdividef(n, D);
}

// K1: chunked two-phase fused kernel. 256 threads, 8 ch/thread, 64 tokens.
// Per 8-row chunk: Phase A = warp-per-row rinv (16 indep LDS.128/lane,
// one butterfly, zero cross-warp math); barrier; Phase B = barrier-free
// conv/silu/dot with rinv via LDS broadcast. x fetched ONCE via a 12-slot
// cp.async ring; mid-B producer issues keep it full.
__global__ void __launch_bounds__(256, 2) score_kernel(
    const float* __restrict__ x, const float* __restrict__ nw,
    const float* __restrict__ cw, const float* __restrict__ pw)
{
    extern __shared__ float4 ring[];    // [RSLOT][512] : 12 x 8KB
    __shared__ float rinv_s[16];        // double-buffered per-row rinv
    __shared__ float spart[TOK][8];     // per-token score warp partials

    const int b    = blockIdx.y;
    const int s0   = blockIdx.x * TOK;
    const int tid  = threadIdx.x;
    const int lane = tid & 31, wid = tid >> 5;
    const int c0   = tid * 8;

    unsigned ring_u32;
    {
        unsigned long long g;
        asm("cvta.to.shared.u64 %0, %1;" : "=l"(g) : "l"(ring));
        ring_u32 = (unsigned)g + (unsigned)(tid * 32);
    }

    // Constants: fold nw into conv taps -> wnv[tap][c] = cw[c][tap]*nw[c]
    u64 wnv2[4][4];
    float gch[8];
#pragma unroll
    for (int j = 0; j < 4; j++) {
        int d = c0 + 2 * j;
        float n0 = nw[d], n1 = nw[d + 1];
#pragma unroll
        for (int wi = 0; wi < 4; wi++)
            wnv2[wi][j] = pk(cw[d * 4 + wi] * n0, cw[(d + 1) * 4 + wi] * n1);
    }
#pragma unroll
    for (int c = 0; c < 8; c++) gch[c] = pw[DV + c0 + c] - pw[c0 + c];

    u64 acc2[4][4];
#pragma unroll
    for (int s = 0; s < 4; s++)
#pragma unroll
        for (int j = 0; j < 4; j++) acc2[s][j] = 0ull;

    const float* xb = x + (size_t)b * SV * DV + c0;

    // Stage 4 rows [first, first+4); one commit group (possibly empty).
    auto produce4 = [&](int first) {
        if (first < 8 * NCHUNK) {
#pragma unroll
            for (int k = 0; k < 4; k++) {
                const int i = first + k;
                const int r = s0 - 3 + i;
                const unsigned dst = ring_u32 + (unsigned)((i % RSLOT) * 8192);
                if (i < NROWS && r >= 0) {
                    const float* src = xb + (size_t)r * DV;
                    cpa16(dst, src);
                    cpa16(dst + 16, src + 4);
                } else {
                    sts_zero16(dst);
                    sts_zero16(dst + 16);
                }
            }
        }
        cpa_commit();
    };

    // Prologue: fill all 12 slots (chunk 0 rows 0-7, chunk 1 rows 0-3)
    produce4(0);
    produce4(4);
    produce4(8);

#pragma unroll 1
    for (int c = 0; c < NCHUNK; c++) {
        cpa_wait<1>();     // this chunk's 8 rows landed (next 4 may be in flight)
        __syncthreads();   // make all threads' cp.async data visible

        // ---- Phase A: warp-per-row rinv (16 independent LDS.128 per lane)
        {
            const int i = 8 * c + wid;
            const float4* rowp = &ring[(i % RSLOT) * 512];
            float ss = 0.f;
#pragma unroll
            for (int j = 0; j < 16; j++) {
                float4 v = rowp[lane + 32 * j];
                ss += v.x * v.x + v.y * v.y + v.z * v.z + v.w * v.w;
            }
            ss = warp_sum(ss);
            if (lane == 0)
                rinv_s[i & 15] = rsqrtf(ss * (1.f / DV) + 1e-5f);
        }
        __syncthreads();   // rinv_s visible

        // ---- Phase B: barrier-free conv/silu/dot over the 8 rows
#pragma unroll
        for (int k = 0; k < 8; k++) {
            const int i = 8 * c + k;
            const float4* slot = &ring[(i % RSLOT) * 512 + tid * 2];
            const float4 a = slot[0], q = slot[1];
            const float ri = rinv_s[i & 15];

            const u64 ri2 = pk(ri, ri);
            u64 xr2[4] = { f2mul(ri2, pk(a.x, a.y)), f2mul(ri2, pk(a.z, a.w)),
                           f2mul(ri2, pk(q.x, q.y)), f2mul(ri2, pk(q.z, q.w)) };

#pragma unroll
            for (int jj = 0; jj < 4; jj++) {
                const int slotidx = (k + 1 + jj) & 3;
#pragma unroll
                for (int j = 0; j < 4; j++)
                    acc2[slotidx][j] =
                        f2fma(wnv2[3 - jj][j], xr2[j], acc2[slotidx][j]);
            }

            if (i >= 3 && i < NROWS) {
                const int slotidx = (k + 1) & 3;
                float v0, v1, v2, v3, v4, v5, v6, v7;
                upk(acc2[slotidx][0], v0, v1);
                upk(acc2[slotidx][1], v2, v3);
                upk(acc2[slotidx][2], v4, v5);
                upk(acc2[slotidx][3], v6, v7);
                float p = silu4(v0, v1, v2, v3, gch[0], gch[1], gch[2], gch[3])
                        + silu4(v4, v5, v6, v7, gch[4], gch[5], gch[6], gch[7]);
                p = warp_sum(p);
                if (lane == 0) spart[i - 3][wid] = p;
            }
            {   // recycle conv slot
                const int slotidx = (k + 1) & 3;
#pragma unroll
                for (int j = 0; j < 4; j++) acc2[slotidx][j] = 0ull;
            }

            // After this thread consumed rows 8c..8c+3, their slots (this
            // thread's own 32B) are free for chunk c+1 rows 4-7.
            if (k == 3) produce4(8 * (c + 1) + 4);
        }
        // Rows 8c+4..8c+7 consumed: stage chunk c+2 rows 0-3.
        produce4(8 * (c + 2));
    }

    __syncthreads();
    if (tid < TOK) {
        const float4* sp = (const float4*)spart[tid];
        float4 t0 = sp[0], t1 = sp[1];
        float t = ((t0.x + t0.y) + (t0.z + t0.w))
                + ((t1.x + t1.y) + (t1.z + t1.w));
        g_mask[b * SV + s0 + tid] = (t > 0.f) ? 1 : 0;
    }
}

// K2: per-batch inclusive scan of masks -> inverse map src[b][c-1] = s -------
__global__ void __launch_bounds__(1024) scan_kernel() {
    const int b   = blockIdx.x;
    const int tid = threadIdx.x;
    for (int j = tid; j < SV; j += 1024) g_src[b * SV + j] = -1;
    __syncthreads();

    int base = tid * 4;
    int m[4], pre[4];
    int sum = 0;
#pragma unroll
    for (int k = 0; k < 4; k++) {
        m[k] = g_mask[b * SV + base + k];
        sum += m[k];
        pre[k] = sum;
    }
    int lane = tid & 31, wid = tid >> 5;
    int v = sum;
#pragma unroll
    for (int o = 1; o < 32; o <<= 1) {
        int t = __shfl_up_sync(0xffffffffu, v, o);
        if (lane >= o) v += t;
    }
    __shared__ int wsum[32];
    if (lane == 31) wsum[wid] = v;
    __syncthreads();
    if (wid == 0) {
        int t = wsum[lane];
#pragma unroll
        for (int o = 1; o < 32; o <<= 1) {
            int u = __shfl_up_sync(0xffffffffu, t, o);
            if (lane >= o) t += u;
        }
        wsum[lane] = t;
    }
    __syncthreads();
    int offset = (wid > 0 ? wsum[wid - 1] : 0) + (v - sum);
#pragma unroll
    for (int k = 0; k < 4; k++) {
        if (m[k]) g_src[b * SV + offset + pre[k] - 1] = base + k;
    }
}

// K3: row-wise gather of x (selected, packed) or zero-fill -------------------
__global__ void __launch_bounds__(256) scatter_kernel(
    const float* __restrict__ x, float* __restrict__ out)
{
    const int row = blockIdx.x;              // 0 .. B*S-1
    const int b   = row >> 12;               // S = 4096
    const int s   = g_src[row];
    float4* o = (float4*)(out + (size_t)row * DV) + threadIdx.x;
    if (s >= 0) {
        const float4* xr =
            (const float4*)(x + ((size_t)(b << 12) + s) * DV) + threadIdx.x;
        float4 v0 = __ldcs(xr);
        float4 v1 = __ldcs(xr + 256);
        __stcs(o, v0);
        __stcs(o + 256, v1);
    } else {
        float4 z = make_float4(0.f, 0.f, 0.f, 0.f);
        __stcs(o, z);
        __stcs(o + 256, z);
    }
}

extern "C" void kernel_launch(void* const* d_in, const int* in_sizes, int n_in,
                              void* d_out, int out_size) {
    const float* x  = (const float*)d_in[0];  // [B,S,D]
    const float* nw = (const float*)d_in[1];  // [D]
    const float* cw = (const float*)d_in[2];  // [D,4]
    const float* pw = (const float*)d_in[3];  // [2,D]
    float* out = (float*)d_out;               // [B,S,D]

    const int ring_bytes = RSLOT * 8192;      // 96KB dynamic smem
    cudaFuncSetAttribute(score_kernel,
                         cudaFuncAttributeMaxDynamicSharedMemorySize,
                         ring_bytes);
    cudaFuncSetAttribute(score_kernel,
                         cudaFuncAttributePreferredSharedMemoryCarveout, 100);

    dim3 g1(SV / TOK, BV);
    score_kernel<<<g1, 256, ring_bytes>>>(x, nw, cw, pw);
    scan_kernel<<<BV, 1024>>>();
    scatter_kernel<<<BV * SV, 256>>>(x, out);
}

// round 12
// speedup vs baseline: 1.2105x; 1.0640x over previous
#include <cuda_runtime.h>

// Problem shape (fixed by the dataset): B=4, S=4096, D=2048, W=4
#define BV 4
#define SV 4096
#define DV 2048
#define TOK 64            // tokens per score block
#define NROWS 67          // real rows (3-row causal halo)
#define NCHUNK 9          // 72 rows incl 5 pad, 8 rows/chunk
#define RSLOT 12          // ring slots (12 x 8KB = 96KB dynamic smem)
#define NGROUP 18         // 4-row producer groups (0..17)

// Scratch (no allocations allowed) ------------------------------------------
__device__ int g_mask[BV * SV];
__device__ int g_src [BV * SV];

// Packed f32x2 helpers --------------------------------------------------------
typedef unsigned long long u64;
static __device__ __forceinline__ u64 pk(float lo, float hi) {
    u64 r; asm("mov.b64 %0,{%1,%2};" : "=l"(r) : "f"(lo), "f"(hi)); return r;
}
static __device__ __forceinline__ void upk(u64 v, float& lo, float& hi) {
    asm("mov.b64 {%0,%1},%2;" : "=f"(lo), "=f"(hi) : "l"(v));
}
static __device__ __forceinline__ u64 f2fma(u64 a, u64 b, u64 c) {
    u64 d; asm("fma.rn.f32x2 %0,%1,%2,%3;" : "=l"(d) : "l"(a), "l"(b), "l"(c)); return d;
}
static __device__ __forceinline__ u64 f2mul(u64 a, u64 b) {
    u64 d; asm("mul.rn.f32x2 %0,%1,%2;" : "=l"(d) : "l"(a), "l"(b)); return d;
}

static __device__ __forceinline__ float warp_sum(float v) {
#pragma unroll
    for (int o = 16; o > 0; o >>= 1)
        v += __shfl_xor_sync(0xffffffffu, v, o);
    return v;
}

// Bulk-copy + mbarrier helpers (UBLKCP path: one instruction per 8KB row,
// bypassing the per-thread 16B/op load-issue granularity) --------------------
static __device__ __forceinline__ unsigned smem_u32(const void* p) {
    unsigned long long g;
    asm("cvta.to.shared.u64 %0, %1;" : "=l"(g) : "l"(p));
    return (unsigned)g;
}
static __device__ __forceinline__ void mbar_init(unsigned mbar, unsigned cnt) {
    asm volatile("mbarrier.init.shared.b64 [%0], %1;" :: "r"(mbar), "r"(cnt)
                 : "memory");
}
static __device__ __forceinline__ void mbar_expect_tx(unsigned mbar,
                                                      unsigned bytes) {
    asm volatile("mbarrier.arrive.expect_tx.shared.b64 _, [%0], %1;"
                 :: "r"(mbar), "r"(bytes) : "memory");
}
static __device__ __forceinline__ void mbar_wait(unsigned mbar,
                                                 unsigned parity) {
    asm volatile(
        "{\n\t.reg .pred P;\n\t"
        "WAIT_%=:\n\t"
        "mbarrier.try_wait.parity.acquire.cta.shared::cta.b64 P, [%0], %1, 0x989680;\n\t"
        "@!P bra WAIT_%=;\n\t"
        "}"
        :: "r"(mbar), "r"(parity) : "memory");
}
static __device__ __forceinline__ void bulk_g2s(unsigned dst, const void* src,
                                                unsigned mbar) {
    asm volatile(
        "cp.async.bulk.shared::cluster.global.mbarrier::complete_tx::bytes "
        "[%0], [%1], %2, [%3];"
        :: "r"(dst), "l"(src), "r"(8192u), "r"(mbar) : "memory");
}

// Sum of 4 silu-gated terms with ONE reciprocal
static __device__ __forceinline__ float silu4(
    float v0, float v1, float v2, float v3,
    float g0, float g1, float g2, float g3)
{
    float d0 = 1.f + __expf(-v0);
    float d1 = 1.f + __expf(-v1);
    float d2 = 1.f + __expf(-v2);
    float d3 = 1.f + __expf(-v3);
    float a0 = g0 * v0, a1 = g1 * v1, a2 = g2 * v2, a3 = g3 * v3;
    float n01 = fmaf(a0, d1, a1 * d0);
    float n23 = fmaf(a2, d3, a3 * d2);
    float D01 = d0 * d1;
    float D23 = d2 * d3;
    float n = fmaf(n01, D23, n23 * D01);
    float D = D01 * D23;
    return __fdividef(n, D);
}

// K1: chunked two-phase fused kernel, bulk-copy edition. 256 threads, 8
// ch/thread, 64 tokens/block. x rows arrive as 8KB cp.async.bulk copies
// (thread0-issued, 4-row groups, 3 parity mbarriers, 12-slot ring). Per
// chunk: Phase A = warp-per-row rinv; barrier; Phase B = conv/silu/dot.
__global__ void __launch_bounds__(256, 2) score_kernel(
    const float* __restrict__ x, const float* __restrict__ nw,
    const float* __restrict__ cw, const float* __restrict__ pw)
{
    extern __shared__ float4 ring[];    // [RSLOT][512] : 12 x 8KB
    __shared__ __align__(16) unsigned long long mbars[3];
    __shared__ float rinv_s[16];        // double-buffered per-row rinv
    // __align__(16): rows are read back as float4 (LDS.128). Static smem
    // layout shifts between builds; R11's crash was this array landing on
    // an 8-byte boundary.
    __shared__ __align__(16) float spart[TOK][8];

    const int b    = blockIdx.y;
    const int s0   = blockIdx.x * TOK;
    const int tid  = threadIdx.x;
    const int lane = tid & 31, wid = tid >> 5;
    const int c0   = tid * 8;

    const unsigned ring_u32 = smem_u32(ring);
    const unsigned mbar_u32 = smem_u32(mbars);
    const float*   xrow     = x + (size_t)b * SV * DV;

    if (tid == 0) {
#pragma unroll
        for (int m = 0; m < 3; m++) mbar_init(mbar_u32 + m * 8, 1);
    }
    __syncthreads();

    // Issue one 4-row group (thread0 only): expect_tx for the real rows,
    // then one 8KB bulk copy per real row. Pad rows are skipped entirely
    // (consumer substitutes zeros).
    auto issue_group = [&](int g) {
        if (g >= NGROUP) return;
        const unsigned mbar = mbar_u32 + (g % 3) * 8;
        int idx[4], cnt = 0;
#pragma unroll
        for (int k = 0; k < 4; k++) {
            const int i = 4 * g + k;
            if (i < NROWS && (s0 - 3 + i) >= 0) idx[cnt++] = i;
        }
        mbar_expect_tx(mbar, (unsigned)cnt * 8192u);
        for (int t = 0; t < cnt; t++) {
            const int i = idx[t];
            bulk_g2s(ring_u32 + (unsigned)((i % RSLOT) * 8192),
                     xrow + (size_t)(s0 - 3 + i) * DV, mbar);
        }
    };

    if (tid == 0) { issue_group(0); issue_group(1); issue_group(2); }

    // Constants: fold nw into conv taps -> wnv[tap][c] = cw[c][tap]*nw[c]
    u64 wnv2[4][4];
    float gch[8];
#pragma unroll
    for (int j = 0; j < 4; j++) {
        int d = c0 + 2 * j;
        float n0 = nw[d], n1 = nw[d + 1];
#pragma unroll
        for (int wi = 0; wi < 4; wi++)
            wnv2[wi][j] = pk(cw[d * 4 + wi] * n0, cw[(d + 1) * 4 + wi] * n1);
    }
#pragma unroll
    for (int c = 0; c < 8; c++) gch[c] = pw[DV + c0 + c] - pw[c0 + c];

    u64 acc2[4][4];
#pragma unroll
    for (int s = 0; s < 4; s++)
#pragma unroll
        for (int j = 0; j < 4; j++) acc2[s][j] = 0ull;

    const float4 fz = make_float4(0.f, 0.f, 0.f, 0.f);

#pragma unroll 1
    for (int c = 0; c < NCHUNK; c++) {
        // Wait for this chunk's two groups (acquire orders TMA writes).
        {
            const int g0g = 2 * c, g1g = 2 * c + 1;
            mbar_wait(mbar_u32 + (g0g % 3) * 8, (unsigned)((g0g / 3) & 1));
            mbar_wait(mbar_u32 + (g1g % 3) * 8, (unsigned)((g1g / 3) & 1));
        }

        // ---- Phase A: warp-per-row rinv (16 independent LDS.128 per lane)
        {
            const int i = 8 * c + wid;
            const bool valid = (i < NROWS) && (s0 - 3 + i >= 0);
            float ri = 0.f;
            if (valid) {
                const float4* rowp = &ring[(i % RSLOT) * 512];
                float ss = 0.f;
#pragma unroll
                for (int j = 0; j < 16; j++) {
                    float4 v = rowp[lane + 32 * j];
                    ss += v.x * v.x + v.y * v.y + v.z * v.z + v.w * v.w;
                }
                ss = warp_sum(ss);
                ri = rsqrtf(ss * (1.f / DV) + 1e-5f);
            }
            if (lane == 0) rinv_s[i & 15] = ri;
        }
        __syncthreads();   // rinv_s visible

        // ---- Phase B: conv/silu/dot over the 8 rows
#pragma unroll
        for (int k = 0; k < 8; k++) {
            const int i = 8 * c + k;
            const bool valid = (i < NROWS) && (s0 - 3 + i >= 0);
            float4 a = fz, q = fz;
            if (valid) {
                const float4* slot = &ring[(i % RSLOT) * 512 + tid * 2];
                a = slot[0]; q = slot[1];
            }
            const float ri = rinv_s[i & 15];

            const u64 ri2 = pk(ri, ri);
            u64 xr2[4] = { f2mul(ri2, pk(a.x, a.y)), f2mul(ri2, pk(a.z, a.w)),
                           f2mul(ri2, pk(q.x, q.y)), f2mul(ri2, pk(q.z, q.w)) };

#pragma unroll
            for (int jj = 0; jj < 4; jj++) {
                const int sl = (k + 1 + jj) & 3;
#pragma unroll
                for (int j = 0; j < 4; j++)
                    acc2[sl][j] = f2fma(wnv2[3 - jj][j], xr2[j], acc2[sl][j]);
            }

            if (i >= 3 && i < NROWS) {
                const int sl = (k + 1) & 3;
                float v0, v1, v2, v3, v4, v5, v6, v7;
                upk(acc2[sl][0], v0, v1);
                upk(acc2[sl][1], v2, v3);
                upk(acc2[sl][2], v4, v5);
                upk(acc2[sl][3], v6, v7);
                float p = silu4(v0, v1, v2, v3, gch[0], gch[1], gch[2], gch[3])
                        + silu4(v4, v5, v6, v7, gch[4], gch[5], gch[6], gch[7]);
                p = warp_sum(p);
                if (lane == 0) spart[i - 3][wid] = p;
            }
            {   // recycle conv slot
                const int sl = (k + 1) & 3;
#pragma unroll
                for (int j = 0; j < 4; j++) acc2[sl][j] = 0ull;
            }
        }

        // All threads done reading this chunk's slots -> refill them.
        __syncthreads();
        if (tid == 0) { issue_group(2 * c + 3); issue_group(2 * c + 4); }
    }

    __syncthreads();
    if (tid < TOK) {
        const float4* sp = (const float4*)spart[tid];
        float4 t0 = sp[0], t1 = sp[1];
        float t = ((t0.x + t0.y) + (t0.z + t0.w))
                + ((t1.x + t1.y) + (t1.z + t1.w));
        g_mask[b * SV + s0 + tid] = (t > 0.f) ? 1 : 0;
    }
}

// K2: per-batch inclusive scan of masks -> inverse map src[b][c-1] = s -------
__global__ void __launch_bounds__(1024) scan_kernel() {
    const int b   = blockIdx.x;
    const int tid = threadIdx.x;
    for (int j = tid; j < SV; j += 1024) g_src[b * SV + j] = -1;
    __syncthreads();

    int base = tid * 4;
    int m[4], pre[4];
    int sum = 0;
#pragma unroll
    for (int k = 0; k < 4; k++) {
        m[k] = g_mask[b * SV + base + k];
        sum += m[k];
        pre[k] = sum;
    }
    int lane = tid & 31, wid = tid >> 5;
    int v = sum;
#pragma unroll
    for (int o = 1; o < 32; o <<= 1) {
        int t = __shfl_up_sync(0xffffffffu, v, o);
        if (lane >= o) v += t;
    }
    __shared__ int wsum[32];
    if (lane == 31) wsum[wid] = v;
    __syncthreads();
    if (wid == 0) {
        int t = wsum[lane];
#pragma unroll
        for (int o = 1; o < 32; o <<= 1) {
            int u = __shfl_up_sync(0xffffffffu, t, o);
            if (lane >= o) t += u;
        }
        wsum[lane] = t;
    }
    __syncthreads();
    int offset = (wid > 0 ? wsum[wid - 1] : 0) + (v - sum);
#pragma unroll
    for (int k = 0; k < 4; k++) {
        if (m[k]) g_src[b * SV + offset + pre[k] - 1] = base + k;
    }
}

// K3: row-wise gather of x (selected, packed) or zero-fill -------------------
__global__ void __launch_bounds__(256) scatter_kernel(
    const float* __restrict__ x, float* __restrict__ out)
{
    const int row = blockIdx.x;              // 0 .. B*S-1
    const int b   = row >> 12;               // S = 4096
    const int s   = g_src[row];
    float4* o = (float4*)(out + (size_t)row * DV) + threadIdx.x;
    if (s >= 0) {
        const float4* xr =
            (const float4*)(x + ((size_t)(b << 12) + s) * DV) + threadIdx.x;
        float4 v0 = __ldcs(xr);
        float4 v1 = __ldcs(xr + 256);
        __stcs(o, v0);
        __stcs(o + 256, v1);
    } else {
        float4 z = make_float4(0.f, 0.f, 0.f, 0.f);
        __stcs(o, z);
        __stcs(o + 256, z);
    }
}

extern "C" void kernel_launch(void* const* d_in, const int* in_sizes, int n_in,
                              void* d_out, int out_size) {
    const float* x  = (const float*)d_in[0];  // [B,S,D]
    const float* nw = (const float*)d_in[1];  // [D]
    const float* cw = (const float*)d_in[2];  // [D,4]
    const float* pw = (const float*)d_in[3];  // [2,D]
    float* out = (float*)d_out;               // [B,S,D]

    const int ring_bytes = RSLOT * 8192;      // 96KB dynamic smem
    cudaFuncSetAttribute(score_kernel,
                         cudaFuncAttributeMaxDynamicSharedMemorySize,
                         ring_bytes);
    cudaFuncSetAttribute(score_kernel,
                         cudaFuncAttributePreferredSharedMemoryCarveout, 100);

    dim3 g1(SV / TOK, BV);
    score_kernel<<<g1, 256, ring_bytes>>>(x, nw, cw, pw);
    scan_kernel<<<BV, 1024>>>();
    scatter_kernel<<<BV * SV, 256>>>(x, out);
}

// round 13
// speedup vs baseline: 1.2913x; 1.0667x over previous
#include <cuda_runtime.h>

// Problem shape (fixed by the dataset): B=4, S=4096, D=2048, W=4
#define BV 4
#define SV 4096
#define DV 2048
#define TOK 64            // tokens per score block
#define NROWS 67          // real rows (3-row causal halo)

// Scratch (no allocations allowed) ------------------------------------------
__device__ int g_mask[BV * SV];
__device__ int g_src [BV * SV];

// Packed f32x2 helpers --------------------------------------------------------
typedef unsigned long long u64;
static __device__ __forceinline__ u64 pk(float lo, float hi) {
    u64 r; asm("mov.b64 %0,{%1,%2};" : "=l"(r) : "f"(lo), "f"(hi)); return r;
}
static __device__ __forceinline__ void upk(u64 v, float& lo, float& hi) {
    asm("mov.b64 {%0,%1},%2;" : "=f"(lo), "=f"(hi) : "l"(v));
}
static __device__ __forceinline__ u64 f2fma(u64 a, u64 b, u64 c) {
    u64 d; asm("fma.rn.f32x2 %0,%1,%2,%3;" : "=l"(d) : "l"(a), "l"(b), "l"(c)); return d;
}
static __device__ __forceinline__ u64 f2mul(u64 a, u64 b) {
    u64 d; asm("mul.rn.f32x2 %0,%1,%2;" : "=l"(d) : "l"(a), "l"(b)); return d;
}

static __device__ __forceinline__ float warp_sum(float v) {
#pragma unroll
    for (int o = 16; o > 0; o >>= 1)
        v += __shfl_xor_sync(0xffffffffu, v, o);
    return v;
}

// Bulk-copy + mbarrier helpers ------------------------------------------------
static __device__ __forceinline__ unsigned smem_u32(const void* p) {
    unsigned long long g;
    asm("cvta.to.shared.u64 %0, %1;" : "=l"(g) : "l"(p));
    return (unsigned)g;
}
static __device__ __forceinline__ void mbar_init(unsigned mbar, unsigned cnt) {
    asm volatile("mbarrier.init.shared.b64 [%0], %1;" :: "r"(mbar), "r"(cnt)
                 : "memory");
}
static __device__ __forceinline__ void mbar_expect_tx(unsigned mbar,
                                                      unsigned bytes) {
    asm volatile("mbarrier.arrive.expect_tx.shared.b64 _, [%0], %1;"
                 :: "r"(mbar), "r"(bytes) : "memory");
}
static __device__ __forceinline__ void mbar_wait(unsigned mbar,
                                                 unsigned parity) {
    asm volatile(
        "{\n\t.reg .pred P;\n\t"
        "WAIT_%=:\n\t"
        "mbarrier.try_wait.parity.acquire.cta.shared::cta.b64 P, [%0], %1, 0x989680;\n\t"
        "@!P bra WAIT_%=;\n\t"
        "}"
        :: "r"(mbar), "r"(parity) : "memory");
}
static __device__ __forceinline__ void bulk_g2s(unsigned dst, const void* src,
                                                unsigned mbar) {
    asm volatile(
        "cp.async.bulk.shared::cluster.global.mbarrier::complete_tx::bytes "
        "[%0], [%1], %2, [%3];"
        :: "r"(dst), "l"(src), "r"(8192u), "r"(mbar) : "memory");
}
static __device__ __forceinline__ void sts_zero16(unsigned dst) {
    asm volatile("st.shared.v4.b32 [%0],{%1,%1,%1,%1};" :: "r"(dst), "r"(0));
}

// Sum of 4 silu-gated terms with ONE reciprocal
static __device__ __forceinline__ float silu4(
    float v0, float v1, float v2, float v3,
    float g0, float g1, float g2, float g3)
{
    float d0 = 1.f + __expf(-v0);
    float d1 = 1.f + __expf(-v1);
    float d2 = 1.f + __expf(-v2);
    float d3 = 1.f + __expf(-v3);
    float a0 = g0 * v0, a1 = g1 * v1, a2 = g2 * v2, a3 = g3 * v3;
    float n01 = fmaf(a0, d1, a1 * d0);
    float n23 = fmaf(a2, d3, a3 * d2);
    float D01 = d0 * d1;
    float D23 = d2 * d3;
    float n = fmaf(n01, D23, n23 * D01);
    float D = D01 * D23;
    return __fdividef(n, D);
}

// Issue a 4-row TMA group. GB = (4g) % 12 is compile-time; mbar index = g%3
// = GB/4. Invalid rows are skipped (expect_tx counts only real rows).
template<int GB>
static __device__ __forceinline__ void issue4(int g, int s0,
                                              unsigned ring_u32,
                                              unsigned mbar_u32,
                                              const float* xrow) {
    if (g >= 18) return;
    const unsigned mbar = mbar_u32 + (GB / 4) * 8;
    int cnt = 0;
#pragma unroll
    for (int k = 0; k < 4; k++) {
        const int i = 4 * g + k;
        if (i < NROWS && (s0 - 3 + i) >= 0) cnt++;
    }
    mbar_expect_tx(mbar, (unsigned)cnt * 8192u);
#pragma unroll
    for (int k = 0; k < 4; k++) {
        const int i = 4 * g + k;
        if (i < NROWS && (s0 - 3 + i) >= 0)
            bulk_g2s(ring_u32 + (unsigned)((GB + k) * 8192),
                     xrow + (size_t)(s0 - 3 + i) * DV, mbar);
    }
}

// One 8-row chunk. CB = (8c) % 12 (compile-time in {0,8,4}); FIRST/LAST gate
// publication only — invalid rows feed never-published accumulators (each
// accumulator is overwritten via tap-0 f2mul before its next use), and block
// 0's halo slots are zero-filled at kernel start, so Phase B is branch-free.
template<int CB, bool FIRST, bool LAST>
static __device__ __forceinline__ void process_chunk(
    int c, int s0, int tid, int lane, int wid,
    const float4* ring, unsigned ring_u32, unsigned mbar_u32,
    const float* xrow, u64 (&acc2)[4][4], const u64 (&wnv2)[4][4],
    const float (&gch)[8], float* rinv_s, float (*pbuf)[32])
{
    constexpr int M0 = (CB == 0) ? 0 : ((CB == 8) ? 2 : 1);   // (2c)%3
    constexpr int M1 = (CB == 0) ? 1 : ((CB == 8) ? 0 : 2);   // (2c+1)%3
    {
        const int g0 = 2 * c, g1 = 2 * c + 1;
        mbar_wait(mbar_u32 + M0 * 8, (unsigned)((g0 / 3) & 1));
        mbar_wait(mbar_u32 + M1 * 8, (unsigned)((g1 / 3) & 1));
    }

    // ---- Phase A: warp-per-row rinv (LAST: rows 3..7 are pads, skip)
    if (!LAST || wid < 3) {
        int slot = CB + wid; if (slot >= 12) slot -= 12;
        const float4* rowp = ring + slot * 512;
        float ss = 0.f;
#pragma unroll
        for (int j = 0; j < 16; j++) {
            const float4 v = rowp[lane + 32 * j];
            ss += v.x * v.x + v.y * v.y + v.z * v.z + v.w * v.w;
        }
        ss = warp_sum(ss);
        if (lane == 0) rinv_s[wid] = rsqrtf(ss * (1.f / DV) + 1e-5f);
    }
    __syncthreads();

    float rv[8];
    {
        const float4 r0 = *(const float4*)rinv_s;
        const float4 r1 = *(const float4*)(rinv_s + 4);
        rv[0] = r0.x; rv[1] = r0.y; rv[2] = r0.z; rv[3] = r0.w;
        rv[4] = r1.x; rv[5] = r1.y; rv[6] = r1.z; rv[7] = r1.w;
    }

    // ---- Phase B: branch-free conv/silu/dot (all slots compile-time)
#pragma unroll
    for (int k = 0; k < 8; k++) {
        const float4* sp = ring + ((CB + k) % 12) * 512 + tid * 2;
        const float4 a = sp[0], q = sp[1];
        const u64 ri2 = pk(rv[k], rv[k]);
        u64 xr2[4] = { f2mul(ri2, pk(a.x, a.y)), f2mul(ri2, pk(a.z, a.w)),
                       f2mul(ri2, pk(q.x, q.y)), f2mul(ri2, pk(q.z, q.w)) };

#pragma unroll
        for (int j = 0; j < 4; j++)          // tap0 OVERWRITES (no resets)
            acc2[k & 3][j] = f2mul(wnv2[0][j], xr2[j]);
#pragma unroll
        for (int j = 0; j < 4; j++)
            acc2[(k + 3) & 3][j] = f2fma(wnv2[1][j], xr2[j], acc2[(k + 3) & 3][j]);
#pragma unroll
        for (int j = 0; j < 4; j++)
            acc2[(k + 2) & 3][j] = f2fma(wnv2[2][j], xr2[j], acc2[(k + 2) & 3][j]);
#pragma unroll
        for (int j = 0; j < 4; j++)
            acc2[(k + 1) & 3][j] = f2fma(wnv2[3][j], xr2[j], acc2[(k + 1) & 3][j]);

        const bool pub = FIRST ? (k >= 3) : (LAST ? (k < 3) : true);
        if (pub) {
            const int sl = (k + 1) & 3;
            float v0, v1, v2, v3, v4, v5, v6, v7;
            upk(acc2[sl][0], v0, v1); upk(acc2[sl][1], v2, v3);
            upk(acc2[sl][2], v4, v5); upk(acc2[sl][3], v6, v7);
            float p = silu4(v0, v1, v2, v3, gch[0], gch[1], gch[2], gch[3])
                    + silu4(v4, v5, v6, v7, gch[4], gch[5], gch[6], gch[7]);
            p += __shfl_xor_sync(0xffffffffu, p, 1);   // 3-level butterfly
            p += __shfl_xor_sync(0xffffffffu, p, 2);
            p += __shfl_xor_sync(0xffffffffu, p, 4);
            if ((lane & 7) == 0)
                pbuf[8 * c + k - 3][wid * 4 + (lane >> 3)] = p;
        }
    }
    __syncthreads();   // all threads done reading this chunk's slots

    if (tid == 0) {    // refill: groups 2c+3 (base CB), 2c+4 (base CB+4)
        issue4<CB>(2 * c + 3, s0, ring_u32, mbar_u32, xrow);
        issue4<(CB + 4) % 12>(2 * c + 4, s0, ring_u32, mbar_u32, xrow);
    }
}

// K1: fused rmsnorm + causal dwconv(W=4) + silu + (p1-p0) dot -> sign/token.
__global__ void __launch_bounds__(256, 2) score_kernel(
    const float* __restrict__ x, const float* __restrict__ nw,
    const float* __restrict__ cw, const float* __restrict__ pw)
{
    extern __shared__ float4 ring[];    // [12][512] : 96KB
    __shared__ __align__(16) u64   mbars[3];
    __shared__ __align__(16) float rinv_s[8];
    __shared__ __align__(16) float pbuf[TOK][32];  // 8KB score partials

    const int b    = blockIdx.y;
    const int s0   = blockIdx.x * TOK;
    const int tid  = threadIdx.x;
    const int lane = tid & 31, wid = tid >> 5;
    const int c0   = tid * 8;

    const unsigned ring_u32 = smem_u32(ring);
    const unsigned mbar_u32 = smem_u32(mbars);
    const float*   xrow     = x + (size_t)b * SV * DV;

    if (tid == 0) {
#pragma unroll
        for (int m = 0; m < 3; m++) mbar_init(mbar_u32 + m * 8, 1);
    }
    // Block 0: zero the 3 halo slots (rows 0..2 never TMA-written there).
    if (blockIdx.x == 0) {
#pragma unroll
        for (int t = 0; t < 6; t++)
            sts_zero16(ring_u32 + (unsigned)(tid * 16 + t * 4096));
    }
    __syncthreads();
    if (tid == 0) {
        issue4<0>(0, s0, ring_u32, mbar_u32, xrow);
        issue4<4>(1, s0, ring_u32, mbar_u32, xrow);
        issue4<8>(2, s0, ring_u32, mbar_u32, xrow);
    }

    // Constants: fold nw into conv taps -> wnv[tap][c] = cw[c][tap]*nw[c]
    u64 wnv2[4][4];
    float gch[8];
#pragma unroll
    for (int j = 0; j < 4; j++) {
        int d = c0 + 2 * j;
        float n0 = nw[d], n1 = nw[d + 1];
#pragma unroll
        for (int wi = 0; wi < 4; wi++)
            wnv2[wi][j] = pk(cw[d * 4 + wi] * n0, cw[(d + 1) * 4 + wi] * n1);
    }
#pragma unroll
    for (int c = 0; c < 8; c++) gch[c] = pw[DV + c0 + c] - pw[c0 + c];

    u64 acc2[4][4];
#pragma unroll
    for (int s = 0; s < 4; s++)
#pragma unroll
        for (int j = 0; j < 4; j++) acc2[s][j] = 0ull;

    // Chunks 0..8; ring base rotates 0,8,4 (compile-time via templates).
    process_chunk<0, true , false>(0, s0, tid, lane, wid, ring, ring_u32,
                                   mbar_u32, xrow, acc2, wnv2, gch, rinv_s, pbuf);
#pragma unroll 1
    for (int cc = 0; cc < 2; cc++) {
        process_chunk<8, false, false>(3 * cc + 1, s0, tid, lane, wid, ring,
                                       ring_u32, mbar_u32, xrow, acc2, wnv2,
                                       gch, rinv_s, pbuf);
        process_chunk<4, false, false>(3 * cc + 2, s0, tid, lane, wid, ring,
                                       ring_u32, mbar_u32, xrow, acc2, wnv2,
                                       gch, rinv_s, pbuf);
        process_chunk<0, false, false>(3 * cc + 3, s0, tid, lane, wid, ring,
                                       ring_u32, mbar_u32, xrow, acc2, wnv2,
                                       gch, rinv_s, pbuf);
    }
    process_chunk<8, false, false>(7, s0, tid, lane, wid, ring, ring_u32,
                                   mbar_u32, xrow, acc2, wnv2, gch, rinv_s, pbuf);
    process_chunk<4, false, true >(8, s0, tid, lane, wid, ring, ring_u32,
                                   mbar_u32, xrow, acc2, wnv2, gch, rinv_s, pbuf);

    __syncthreads();
    if (tid < TOK) {
        const float4* sp = (const float4*)pbuf[tid];
        float t = 0.f;
#pragma unroll
        for (int j = 0; j < 8; j++) {
            const float4 v = sp[j];
            t += ((v.x + v.y) + (v.z + v.w));
        }
        g_mask[b * SV + s0 + tid] = (t > 0.f) ? 1 : 0;
    }
}

// K2: per-batch inclusive scan of masks -> inverse map src[b][c-1] = s -------
__global__ void __launch_bounds__(1024) scan_kernel() {
    const int b   = blockIdx.x;
    const int tid = threadIdx.x;
    for (int j = tid; j < SV; j += 1024) g_src[b * SV + j] = -1;
    __syncthreads();

    int base = tid * 4;
    int m[4], pre[4];
    int sum = 0;
#pragma unroll
    for (int k = 0; k < 4; k++) {
        m[k] = g_mask[b * SV + base + k];
        sum += m[k];
        pre[k] = sum;
    }
    int lane = tid & 31, wid = tid >> 5;
    int v = sum;
#pragma unroll
    for (int o = 1; o < 32; o <<= 1) {
        int t = __shfl_up_sync(0xffffffffu, v, o);
        if (lane >= o) v += t;
    }
    __shared__ int wsum[32];
    if (lane == 31) wsum[wid] = v;
    __syncthreads();
    if (wid == 0) {
        int t = wsum[lane];
#pragma unroll
        for (int o = 1; o < 32; o <<= 1) {
            int u = __shfl_up_sync(0xffffffffu, t, o);
            if (lane >= o) t += u;
        }
        wsum[lane] = t;
    }
    __syncthreads();
    int offset = (wid > 0 ? wsum[wid - 1] : 0) + (v - sum);
#pragma unroll
    for (int k = 0; k < 4; k++) {
        if (m[k]) g_src[b * SV + offset + pre[k] - 1] = base + k;
    }
}

// K3: row-wise gather of x (selected, packed) or zero-fill -------------------
__global__ void __launch_bounds__(256) scatter_kernel(
    const float* __restrict__ x, float* __restrict__ out)
{
    const int row = blockIdx.x;              // 0 .. B*S-1
    const int b   = row >> 12;               // S = 4096
    const int s   = g_src[row];
    float4* o = (float4*)(out + (size_t)row * DV) + threadIdx.x;
    if (s >= 0) {
        const float4* xr =
            (const float4*)(x + ((size_t)(b << 12) + s) * DV) + threadIdx.x;
        float4 v0 = __ldcs(xr);
        float4 v1 = __ldcs(xr + 256);
        __stcs(o, v0);
        __stcs(o + 256, v1);
    } else {
        float4 z = make_float4(0.f, 0.f, 0.f, 0.f);
        __stcs(o, z);
        __stcs(o + 256, z);
    }
}

extern "C" void kernel_launch(void* const* d_in, const int* in_sizes, int n_in,
                              void* d_out, int out_size) {
    const float* x  = (const float*)d_in[0];  // [B,S,D]
    const float* nw = (const float*)d_in[1];  // [D]
    const float* cw = (const float*)d_in[2];  // [D,4]
    const float* pw = (const float*)d_in[3];  // [2,D]
    float* out = (float*)d_out;               // [B,S,D]

    const int ring_bytes = 12 * 8192;         // 96KB dynamic smem
    cudaFuncSetAttribute(score_kernel,
                         cudaFuncAttributeMaxDynamicSharedMemorySize,
                         ring_bytes);
    cudaFuncSetAttribute(score_kernel,
                         cudaFuncAttributePreferredSharedMemoryCarveout, 100);

    dim3 g1(SV / TOK, BV);
    score_kernel<<<g1, 256, ring_bytes>>>(x, nw, cw, pw);
    scan_kernel<<<BV, 1024>>>();
    scatter_kernel<<<BV * SV, 256>>>(x, out);
}

// round 14
// speedup vs baseline: 1.3225x; 1.0242x over previous
#include <cuda_runtime.h>

// Problem shape (fixed by the dataset): B=4, S=4096, D=2048, W=4
#define BV 4
#define SV 4096
#define DV 2048
#define TOK 32            // tokens per score block
#define NROWS 35          // real rows (3-row causal halo)
#define NGROUP 10         // 4-row TMA groups (rows 0..39, 36..39 pad)
#define THREADS 512       // 4 channels/thread

// Scratch (no allocations allowed) ------------------------------------------
__device__ int g_mask[BV * SV];
__device__ int g_src [BV * SV];

// Packed f32x2 helpers --------------------------------------------------------
typedef unsigned long long u64;
static __device__ __forceinline__ u64 pk(float lo, float hi) {
    u64 r; asm("mov.b64 %0,{%1,%2};" : "=l"(r) : "f"(lo), "f"(hi)); return r;
}
static __device__ __forceinline__ void upk(u64 v, float& lo, float& hi) {
    asm("mov.b64 {%0,%1},%2;" : "=f"(lo), "=f"(hi) : "l"(v));
}
static __device__ __forceinline__ u64 f2fma(u64 a, u64 b, u64 c) {
    u64 d; asm("fma.rn.f32x2 %0,%1,%2,%3;" : "=l"(d) : "l"(a), "l"(b), "l"(c)); return d;
}
static __device__ __forceinline__ u64 f2mul(u64 a, u64 b) {
    u64 d; asm("mul.rn.f32x2 %0,%1,%2;" : "=l"(d) : "l"(a), "l"(b)); return d;
}

static __device__ __forceinline__ float warp_sum(float v) {
#pragma unroll
    for (int o = 16; o > 0; o >>= 1)
        v += __shfl_xor_sync(0xffffffffu, v, o);
    return v;
}

// Bulk-copy + mbarrier helpers ------------------------------------------------
static __device__ __forceinline__ unsigned smem_u32(const void* p) {
    unsigned long long g;
    asm("cvta.to.shared.u64 %0, %1;" : "=l"(g) : "l"(p));
    return (unsigned)g;
}
static __device__ __forceinline__ void mbar_init(unsigned mbar, unsigned cnt) {
    asm volatile("mbarrier.init.shared.b64 [%0], %1;" :: "r"(mbar), "r"(cnt)
                 : "memory");
}
static __device__ __forceinline__ void mbar_expect_tx(unsigned mbar,
                                                      unsigned bytes) {
    asm volatile("mbarrier.arrive.expect_tx.shared.b64 _, [%0], %1;"
                 :: "r"(mbar), "r"(bytes) : "memory");
}
static __device__ __forceinline__ void mbar_wait(unsigned mbar,
                                                 unsigned parity) {
    asm volatile(
        "{\n\t.reg .pred P;\n\t"
        "WAIT_%=:\n\t"
        "mbarrier.try_wait.parity.acquire.cta.shared::cta.b64 P, [%0], %1, 0x989680;\n\t"
        "@!P bra WAIT_%=;\n\t"
        "}"
        :: "r"(mbar), "r"(parity) : "memory");
}
static __device__ __forceinline__ void bulk_g2s(unsigned dst, const void* src,
                                                unsigned mbar) {
    asm volatile(
        "cp.async.bulk.shared::cluster.global.mbarrier::complete_tx::bytes "
        "[%0], [%1], %2, [%3];"
        :: "r"(dst), "l"(src), "r"(8192u), "r"(mbar) : "memory");
}
static __device__ __forceinline__ void sts_zero16(unsigned dst) {
    asm volatile("st.shared.v4.b32 [%0],{%1,%1,%1,%1};" :: "r"(dst), "r"(0));
}

// Sum of 4 silu-gated terms with ONE reciprocal
static __device__ __forceinline__ float silu4(
    float v0, float v1, float v2, float v3,
    float g0, float g1, float g2, float g3)
{
    float d0 = 1.f + __expf(-v0);
    float d1 = 1.f + __expf(-v1);
    float d2 = 1.f + __expf(-v2);
    float d3 = 1.f + __expf(-v3);
    float a0 = g0 * v0, a1 = g1 * v1, a2 = g2 * v2, a3 = g3 * v3;
    float n01 = fmaf(a0, d1, a1 * d0);
    float n23 = fmaf(a2, d3, a3 * d2);
    float D01 = d0 * d1;
    float D23 = d2 * d3;
    float n = fmaf(n01, D23, n23 * D01);
    float D = D01 * D23;
    return __fdividef(n, D);
}

// Issue a 4-row TMA group. GB = (4g) % 12 compile-time; mbar = GB/4.
template<int GB>
static __device__ __forceinline__ void issue4(int g, int s0,
                                              unsigned ring_u32,
                                              unsigned mbar_u32,
                                              const float* xrow) {
    if (g >= NGROUP) return;
    const unsigned mbar = mbar_u32 + (GB / 4) * 8;
    int cnt = 0;
#pragma unroll
    for (int k = 0; k < 4; k++) {
        const int i = 4 * g + k;
        if (i < NROWS && (s0 - 3 + i) >= 0) cnt++;
    }
    mbar_expect_tx(mbar, (unsigned)cnt * 8192u);
#pragma unroll
    for (int k = 0; k < 4; k++) {
        const int i = 4 * g + k;
        if (i < NROWS && (s0 - 3 + i) >= 0)
            bulk_g2s(ring_u32 + (unsigned)((GB + k) * 8192),
                     xrow + (size_t)(s0 - 3 + i) * DV, mbar);
    }
}

// One 8-row chunk (512 threads, 4 ch/thread). CB = (8c)%12 in {0,8,4}.
// Invalid rows feed never-published accumulators; block 0's halo slots are
// zero-filled at start, so Phase B is branch-free.
template<int CB, bool FIRST, bool LAST>
static __device__ __forceinline__ void process_chunk(
    int c, int s0, int tid, int lane, int wid,
    const float4* ring, unsigned ring_u32, unsigned mbar_u32,
    const float* xrow, u64 (&acc2)[4][2], const u64 (&wnv2)[4][2],
    const float (&gch)[4], float* rinv_s, float (*pbuf)[64])
{
    constexpr int M0 = (CB == 0) ? 0 : ((CB == 8) ? 2 : 1);   // (2c)%3
    constexpr int M1 = (CB == 0) ? 1 : ((CB == 8) ? 0 : 2);   // (2c+1)%3
    {
        const int g0 = 2 * c, g1 = 2 * c + 1;
        mbar_wait(mbar_u32 + M0 * 8, (unsigned)((g0 / 3) & 1));
        mbar_wait(mbar_u32 + M1 * 8, (unsigned)((g1 / 3) & 1));
    }

    // ---- Phase A: warp-per-row rinv (warps 0-7; LAST: rows 3..7 are pads)
    if (wid < (LAST ? 3 : 8)) {
        int slot = CB + wid; if (slot >= 12) slot -= 12;
        const float4* rowp = ring + slot * 512;
        float ss = 0.f;
#pragma unroll
        for (int j = 0; j < 16; j++) {
            const float4 v = rowp[lane + 32 * j];
            ss += v.x * v.x + v.y * v.y + v.z * v.z + v.w * v.w;
        }
        ss = warp_sum(ss);
        if (lane == 0) rinv_s[wid] = rsqrtf(ss * (1.f / DV) + 1e-5f);
    }
    __syncthreads();

    float rv[8];
    {
        const float4 r0 = *(const float4*)rinv_s;
        const float4 r1 = *(const float4*)(rinv_s + 4);
        rv[0] = r0.x; rv[1] = r0.y; rv[2] = r0.z; rv[3] = r0.w;
        rv[4] = r1.x; rv[5] = r1.y; rv[6] = r1.z; rv[7] = r1.w;
    }

    // ---- Phase B: branch-free conv/silu/dot (slots compile-time)
#pragma unroll
    for (int k = 0; k < 8; k++) {
        const float4 a = ring[((CB + k) % 12) * 512 + tid];
        const u64 ri2 = pk(rv[k], rv[k]);
        u64 xr2[2] = { f2mul(ri2, pk(a.x, a.y)), f2mul(ri2, pk(a.z, a.w)) };

#pragma unroll
        for (int j = 0; j < 2; j++)          // tap0 OVERWRITES (no resets)
            acc2[k & 3][j] = f2mul(wnv2[0][j], xr2[j]);
#pragma unroll
        for (int j = 0; j < 2; j++)
            acc2[(k + 3) & 3][j] = f2fma(wnv2[1][j], xr2[j], acc2[(k + 3) & 3][j]);
#pragma unroll
        for (int j = 0; j < 2; j++)
            acc2[(k + 2) & 3][j] = f2fma(wnv2[2][j], xr2[j], acc2[(k + 2) & 3][j]);
#pragma unroll
        for (int j = 0; j < 2; j++)
            acc2[(k + 1) & 3][j] = f2fma(wnv2[3][j], xr2[j], acc2[(k + 1) & 3][j]);

        const bool pub = FIRST ? (k >= 3) : (LAST ? (k < 3) : true);
        if (pub) {
            const int sl = (k + 1) & 3;
            float v0, v1, v2, v3;
            upk(acc2[sl][0], v0, v1); upk(acc2[sl][1], v2, v3);
            float p = silu4(v0, v1, v2, v3, gch[0], gch[1], gch[2], gch[3]);
            p += __shfl_xor_sync(0xffffffffu, p, 1);   // 3-level butterfly
            p += __shfl_xor_sync(0xffffffffu, p, 2);
            p += __shfl_xor_sync(0xffffffffu, p, 4);
            if ((lane & 7) == 0)
                pbuf[8 * c + k - 3][wid * 4 + (lane >> 3)] = p;
        }
    }
    __syncthreads();   // all threads done reading this chunk's slots

    if (tid == 0) {    // refill: groups 2c+3 (base CB), 2c+4 (base CB+4)
        issue4<CB>(2 * c + 3, s0, ring_u32, mbar_u32, xrow);
        issue4<(CB + 4) % 12>(2 * c + 4, s0, ring_u32, mbar_u32, xrow);
    }
}

// K1: fused rmsnorm + causal dwconv(W=4) + silu + (p1-p0) dot -> sign/token.
__global__ void __launch_bounds__(THREADS, 2) score_kernel(
    const float* __restrict__ x, const float* __restrict__ nw,
    const float* __restrict__ cw, const float* __restrict__ pw)
{
    extern __shared__ float4 ring[];    // [12][512] : 96KB
    __shared__ __align__(16) u64   mbars[3];
    __shared__ __align__(16) float rinv_s[8];
    __shared__ __align__(16) float pbuf[TOK][64];  // 8KB score partials

    const int b    = blockIdx.y;
    const int s0   = blockIdx.x * TOK;
    const int tid  = threadIdx.x;
    const int lane = tid & 31, wid = tid >> 5;
    const int c0   = tid * 4;

    const unsigned ring_u32 = smem_u32(ring);
    const unsigned mbar_u32 = smem_u32(mbars);
    const float*   xrow     = x + (size_t)b * SV * DV;

    if (tid == 0) {
#pragma unroll
        for (int m = 0; m < 3; m++) mbar_init(mbar_u32 + m * 8, 1);
    }
    // Block 0: zero the 3 halo slots (rows 0..2 never TMA-written there).
    if (blockIdx.x == 0) {
#pragma unroll
        for (int t = 0; t < 3; t++)
            sts_zero16(ring_u32 + (unsigned)(tid * 16 + t * 8192));
    }
    __syncthreads();
    if (tid == 0) {
        issue4<0>(0, s0, ring_u32, mbar_u32, xrow);
        issue4<4>(1, s0, ring_u32, mbar_u32, xrow);
        issue4<8>(2, s0, ring_u32, mbar_u32, xrow);
    }

    // Constants: fold nw into conv taps -> wnv[tap][c] = cw[c][tap]*nw[c]
    u64 wnv2[4][2];
    float gch[4];
#pragma unroll
    for (int j = 0; j < 2; j++) {
        int d = c0 + 2 * j;
        float n0 = nw[d], n1 = nw[d + 1];
#pragma unroll
        for (int wi = 0; wi < 4; wi++)
            wnv2[wi][j] = pk(cw[d * 4 + wi] * n0, cw[(d + 1) * 4 + wi] * n1);
    }
#pragma unroll
    for (int c = 0; c < 4; c++) gch[c] = pw[DV + c0 + c] - pw[c0 + c];

    u64 acc2[4][2];
#pragma unroll
    for (int s = 0; s < 4; s++) { acc2[s][0] = 0ull; acc2[s][1] = 0ull; }

    // Chunks 0..4; ring base rotates 0,8,4,0,8 (compile-time).
    process_chunk<0, true , false>(0, s0, tid, lane, wid, ring, ring_u32,
                                   mbar_u32, xrow, acc2, wnv2, gch, rinv_s, pbuf);
    process_chunk<8, false, false>(1, s0, tid, lane, wid, ring, ring_u32,
                                   mbar_u32, xrow, acc2, wnv2, gch, rinv_s, pbuf);
    process_chunk<4, false, false>(2, s0, tid, lane, wid, ring, ring_u32,
                                   mbar_u32, xrow, acc2, wnv2, gch, rinv_s, pbuf);
    process_chunk<0, false, false>(3, s0, tid, lane, wid, ring, ring_u32,
                                   mbar_u32, xrow, acc2, wnv2, gch, rinv_s, pbuf);
    process_chunk<8, false, true >(4, s0, tid, lane, wid, ring, ring_u32,
                                   mbar_u32, xrow, acc2, wnv2, gch, rinv_s, pbuf);

    __syncthreads();
    if (tid < TOK) {
        const float4* sp = (const float4*)pbuf[tid];
        float t = 0.f;
#pragma unroll
        for (int j = 0; j < 16; j++) {
            const float4 v = sp[j];
            t += ((v.x + v.y) + (v.z + v.w));
        }
        g_mask[b * SV + s0 + tid] = (t > 0.f) ? 1 : 0;
    }
}

// K2: per-batch inclusive scan of masks -> inverse map src[b][c-1] = s -------
__global__ void __launch_bounds__(1024) scan_kernel() {
    const int b   = blockIdx.x;
    const int tid = threadIdx.x;
    for (int j = tid; j < SV; j += 1024) g_src[b * SV + j] = -1;
    __syncthreads();

    int base = tid * 4;
    int m[4], pre[4];
    int sum = 0;
#pragma unroll
    for (int k = 0; k < 4; k++) {
        m[k] = g_mask[b * SV + base + k];
        sum += m[k];
        pre[k] = sum;
    }
    int lane = tid & 31, wid = tid >> 5;
    int v = sum;
#pragma unroll
    for (int o = 1; o < 32; o <<= 1) {
        int t = __shfl_up_sync(0xffffffffu, v, o);
        if (lane >= o) v += t;
    }
    __shared__ int wsum[32];
    if (lane == 31) wsum[wid] = v;
    __syncthreads();
    if (wid == 0) {
        int t = wsum[lane];
#pragma unroll
        for (int o = 1; o < 32; o <<= 1) {
            int u = __shfl_up_sync(0xffffffffu, t, o);
            if (lane >= o) t += u;
        }
        wsum[lane] = t;
    }
    __syncthreads();
    int offset = (wid > 0 ? wsum[wid - 1] : 0) + (v - sum);
#pragma unroll
    for (int k = 0; k < 4; k++) {
        if (m[k]) g_src[b * SV + offset + pre[k] - 1] = base + k;
    }
}

// K3: row-wise gather of x (selected, packed) or zero-fill -------------------
__global__ void __launch_bounds__(256) scatter_kernel(
    const float* __restrict__ x, float* __restrict__ out)
{
    const int row = blockIdx.x;              // 0 .. B*S-1
    const int b   = row >> 12;               // S = 4096
    const int s   = g_src[row];
    float4* o = (float4*)(out + (size_t)row * DV) + threadIdx.x;
    if (s >= 0) {
        const float4* xr =
            (const float4*)(x + ((size_t)(b << 12) + s) * DV) + threadIdx.x;
        float4 v0 = __ldcs(xr);
        float4 v1 = __ldcs(xr + 256);
        __stcs(o, v0);
        __stcs(o + 256, v1);
    } else {
        float4 z = make_float4(0.f, 0.f, 0.f, 0.f);
        __stcs(o, z);
        __stcs(o + 256, z);
    }
}

extern "C" void kernel_launch(void* const* d_in, const int* in_sizes, int n_in,
                              void* d_out, int out_size) {
    const float* x  = (const float*)d_in[0];  // [B,S,D]
    const float* nw = (const float*)d_in[1];  // [D]
    const float* cw = (const float*)d_in[2];  // [D,4]
    const float* pw = (const float*)d_in[3];  // [2,D]
    float* out = (float*)d_out;               // [B,S,D]

    const int ring_bytes = 12 * 8192;         // 96KB dynamic smem
    cudaFuncSetAttribute(score_kernel,
                         cudaFuncAttributeMaxDynamicSharedMemorySize,
                         ring_bytes);
    cudaFuncSetAttribute(score_kernel,
                         cudaFuncAttributePreferredSharedMemoryCarveout, 100);

    dim3 g1(SV / TOK, BV);
    score_kernel<<<g1, THREADS, ring_bytes>>>(x, nw, cw, pw);
    scan_kernel<<<BV, 1024>>>();
    scatter_kernel<<<BV * SV, 256>>>(x, out);
}

// round 15
// speedup vs baseline: 1.3791x; 1.0428x over previous
#include <cuda_runtime.h>

// Problem shape (fixed by the dataset): B=4, S=4096, D=2048, W=4
#define BV 4
#define SV 4096
#define DV 2048
#define TOK 32            // tokens per score block
#define NROWS 35          // real rows (3-row causal halo)
#define NGROUP 10         // 4-row TMA groups (rows 0..39, 36..39 pad)
#define THREADS 512       // 4 channels/thread

// Scratch (no allocations allowed) ------------------------------------------
__device__ int g_mask[BV * SV];
__device__ int g_src [BV * SV];

// Packed f32x2 helpers --------------------------------------------------------
typedef unsigned long long u64;
static __device__ __forceinline__ u64 pk(float lo, float hi) {
    u64 r; asm("mov.b64 %0,{%1,%2};" : "=l"(r) : "f"(lo), "f"(hi)); return r;
}
static __device__ __forceinline__ void upk(u64 v, float& lo, float& hi) {
    asm("mov.b64 {%0,%1},%2;" : "=f"(lo), "=f"(hi) : "l"(v));
}
static __device__ __forceinline__ u64 f2fma(u64 a, u64 b, u64 c) {
    u64 d; asm("fma.rn.f32x2 %0,%1,%2,%3;" : "=l"(d) : "l"(a), "l"(b), "l"(c)); return d;
}
static __device__ __forceinline__ u64 f2mul(u64 a, u64 b) {
    u64 d; asm("mul.rn.f32x2 %0,%1,%2;" : "=l"(d) : "l"(a), "l"(b)); return d;
}

static __device__ __forceinline__ float warp_sum(float v) {
#pragma unroll
    for (int o = 16; o > 0; o >>= 1)
        v += __shfl_xor_sync(0xffffffffu, v, o);
    return v;
}

// Bulk-copy + mbarrier helpers ------------------------------------------------
static __device__ __forceinline__ unsigned smem_u32(const void* p) {
    unsigned long long g;
    asm("cvta.to.shared.u64 %0, %1;" : "=l"(g) : "l"(p));
    return (unsigned)g;
}
static __device__ __forceinline__ void mbar_init(unsigned mbar, unsigned cnt) {
    asm volatile("mbarrier.init.shared.b64 [%0], %1;" :: "r"(mbar), "r"(cnt)
                 : "memory");
}
static __device__ __forceinline__ void mbar_expect_tx(unsigned mbar,
                                                      unsigned bytes) {
    asm volatile("mbarrier.arrive.expect_tx.shared.b64 _, [%0], %1;"
                 :: "r"(mbar), "r"(bytes) : "memory");
}
static __device__ __forceinline__ void mbar_wait(unsigned mbar,
                                                 unsigned parity) {
    asm volatile(
        "{\n\t.reg .pred P;\n\t"
        "WAIT_%=:\n\t"
        "mbarrier.try_wait.parity.acquire.cta.shared::cta.b64 P, [%0], %1, 0x989680;\n\t"
        "@!P bra WAIT_%=;\n\t"
        "}"
        :: "r"(mbar), "r"(parity) : "memory");
}
static __device__ __forceinline__ void bulk_g2s(unsigned dst, const void* src,
                                                unsigned mbar) {
    asm volatile(
        "cp.async.bulk.shared::cluster.global.mbarrier::complete_tx::bytes "
        "[%0], [%1], %2, [%3];"
        :: "r"(dst), "l"(src), "r"(8192u), "r"(mbar) : "memory");
}
static __device__ __forceinline__ void sts_zero16(unsigned dst) {
    asm volatile("st.shared.v4.b32 [%0],{%1,%1,%1,%1};" :: "r"(dst), "r"(0));
}

// Sum of 4 silu-gated terms with ONE reciprocal
static __device__ __forceinline__ float silu4(
    float v0, float v1, float v2, float v3,
    float g0, float g1, float g2, float g3)
{
    float d0 = 1.f + __expf(-v0);
    float d1 = 1.f + __expf(-v1);
    float d2 = 1.f + __expf(-v2);
    float d3 = 1.f + __expf(-v3);
    float a0 = g0 * v0, a1 = g1 * v1, a2 = g2 * v2, a3 = g3 * v3;
    float n01 = fmaf(a0, d1, a1 * d0);
    float n23 = fmaf(a2, d3, a3 * d2);
    float D01 = d0 * d1;
    float D23 = d2 * d3;
    float n = fmaf(n01, D23, n23 * D01);
    float D = D01 * D23;
    return __fdividef(n, D);
}

// Issue a 4-row TMA group. GB = (4g) % 12 compile-time; mbar = GB/4.
template<int GB>
static __device__ __forceinline__ void issue4(int g, int s0,
                                              unsigned ring_u32,
                                              unsigned mbar_u32,
                                              const float* xrow) {
    if (g >= NGROUP) return;
    const unsigned mbar = mbar_u32 + (GB / 4) * 8;
    int cnt = 0;
#pragma unroll
    for (int k = 0; k < 4; k++) {
        const int i = 4 * g + k;
        if (i < NROWS && (s0 - 3 + i) >= 0) cnt++;
    }
    mbar_expect_tx(mbar, (unsigned)cnt * 8192u);
#pragma unroll
    for (int k = 0; k < 4; k++) {
        const int i = 4 * g + k;
        if (i < NROWS && (s0 - 3 + i) >= 0)
            bulk_g2s(ring_u32 + (unsigned)((GB + k) * 8192),
                     xrow + (size_t)(s0 - 3 + i) * DV, mbar);
    }
}

// One 8-row chunk (512 threads, 4 ch/thread). CB = (8c)%12 in {0,8,4}.
// Mid-chunk TMA issue: after k=3 all reads of slots CB..CB+3 are done, so
// group 2c+3 (which reuses those slots) is issued HALF A CHUNK early,
// removing the zero-slack blocking wait at the head of chunk c+1.
template<int CB, bool FIRST, bool LAST>
static __device__ __forceinline__ void process_chunk(
    int c, int s0, int tid, int lane, int wid,
    const float4* ring, unsigned ring_u32, unsigned mbar_u32,
    const float* xrow, u64 (&acc2)[4][2], const u64 (&wnv2)[4][2],
    const float (&gch)[4], float* rinv_s, float (*pbuf)[64])
{
    constexpr int M0 = (CB == 0) ? 0 : ((CB == 8) ? 2 : 1);   // (2c)%3
    constexpr int M1 = (CB == 0) ? 1 : ((CB == 8) ? 0 : 2);   // (2c+1)%3
    {
        const int g0 = 2 * c, g1 = 2 * c + 1;
        mbar_wait(mbar_u32 + M0 * 8, (unsigned)((g0 / 3) & 1));
        mbar_wait(mbar_u32 + M1 * 8, (unsigned)((g1 / 3) & 1));
    }

    // ---- Phase A: warp-per-row rinv (warps 0-7; LAST: rows 3..7 are pads)
    if (wid < (LAST ? 3 : 8)) {
        int slot = CB + wid; if (slot >= 12) slot -= 12;
        const float4* rowp = ring + slot * 512;
        float ss = 0.f;
#pragma unroll
        for (int j = 0; j < 16; j++) {
            const float4 v = rowp[lane + 32 * j];
            ss += v.x * v.x + v.y * v.y + v.z * v.z + v.w * v.w;
        }
        ss = warp_sum(ss);
        if (lane == 0) rinv_s[wid] = rsqrtf(ss * (1.f / DV) + 1e-5f);
    }
    __syncthreads();

    float rv[8];
    {
        const float4 r0 = *(const float4*)rinv_s;
        const float4 r1 = *(const float4*)(rinv_s + 4);
        rv[0] = r0.x; rv[1] = r0.y; rv[2] = r0.z; rv[3] = r0.w;
        rv[4] = r1.x; rv[5] = r1.y; rv[6] = r1.z; rv[7] = r1.w;
    }

    // ---- Phase B: branch-free conv/silu/dot (slots compile-time)
#pragma unroll
    for (int k = 0; k < 8; k++) {
        const float4 a = ring[((CB + k) % 12) * 512 + tid];
        const u64 ri2 = pk(rv[k], rv[k]);
        u64 xr2[2] = { f2mul(ri2, pk(a.x, a.y)), f2mul(ri2, pk(a.z, a.w)) };

#pragma unroll
        for (int j = 0; j < 2; j++)          // tap0 OVERWRITES (no resets)
            acc2[k & 3][j] = f2mul(wnv2[0][j], xr2[j]);
#pragma unroll
        for (int j = 0; j < 2; j++)
            acc2[(k + 3) & 3][j] = f2fma(wnv2[1][j], xr2[j], acc2[(k + 3) & 3][j]);
#pragma unroll
        for (int j = 0; j < 2; j++)
            acc2[(k + 2) & 3][j] = f2fma(wnv2[2][j], xr2[j], acc2[(k + 2) & 3][j]);
#pragma unroll
        for (int j = 0; j < 2; j++)
            acc2[(k + 1) & 3][j] = f2fma(wnv2[3][j], xr2[j], acc2[(k + 1) & 3][j]);

        const bool pub = FIRST ? (k >= 3) : (LAST ? (k < 3) : true);
        if (pub) {
            const int sl = (k + 1) & 3;
            float v0, v1, v2, v3;
            upk(acc2[sl][0], v0, v1); upk(acc2[sl][1], v2, v3);
            float p = silu4(v0, v1, v2, v3, gch[0], gch[1], gch[2], gch[3]);
            p += __shfl_xor_sync(0xffffffffu, p, 1);   // 3-level butterfly
            p += __shfl_xor_sync(0xffffffffu, p, 2);
            p += __shfl_xor_sync(0xffffffffu, p, 4);
            if ((lane & 7) == 0)
                pbuf[8 * c + k - 3][wid * 4 + (lane >> 3)] = p;
        }

        // Mid-chunk refill: slots CB..CB+3 fully consumed by every thread.
        if (k == 3) {
            __syncthreads();
            if (tid == 0)
                issue4<CB>(2 * c + 3, s0, ring_u32, mbar_u32, xrow);
        }
    }
    __syncthreads();   // all threads done reading slots CB+4..CB+7

    if (tid == 0)      // refill the back half: group 2c+4 (base CB+4)
        issue4<(CB + 4) % 12>(2 * c + 4, s0, ring_u32, mbar_u32, xrow);
}

// K1: fused rmsnorm + causal dwconv(W=4) + silu + (p1-p0) dot -> sign/token.
__global__ void __launch_bounds__(THREADS, 2) score_kernel(
    const float* __restrict__ x, const float* __restrict__ nw,
    const float* __restrict__ cw, const float* __restrict__ pw)
{
    extern __shared__ float4 ring[];    // [12][512] : 96KB
    __shared__ __align__(16) u64   mbars[3];
    __shared__ __align__(16) float rinv_s[8];
    __shared__ __align__(16) float pbuf[TOK][64];  // 8KB score partials

    const int b    = blockIdx.y;
    const int s0   = blockIdx.x * TOK;
    const int tid  = threadIdx.x;
    const int lane = tid & 31, wid = tid >> 5;
    const int c0   = tid * 4;

    const unsigned ring_u32 = smem_u32(ring);
    const unsigned mbar_u32 = smem_u32(mbars);
    const float*   xrow     = x + (size_t)b * SV * DV;

    if (tid == 0) {
#pragma unroll
        for (int m = 0; m < 3; m++) mbar_init(mbar_u32 + m * 8, 1);
    }
    // Block 0: zero the 3 halo slots (rows 0..2 never TMA-written there).
    if (blockIdx.x == 0) {
#pragma unroll
        for (int t = 0; t < 3; t++)
            sts_zero16(ring_u32 + (unsigned)(tid * 16 + t * 8192));
    }
    __syncthreads();
    if (tid == 0) {
        issue4<0>(0, s0, ring_u32, mbar_u32, xrow);
        issue4<4>(1, s0, ring_u32, mbar_u32, xrow);
        issue4<8>(2, s0, ring_u32, mbar_u32, xrow);
    }

    // Constants: fold nw into conv taps -> wnv[tap][c] = cw[c][tap]*nw[c]
    u64 wnv2[4][2];
    float gch[4];
#pragma unroll
    for (int j = 0; j < 2; j++) {
        int d = c0 + 2 * j;
        float n0 = nw[d], n1 = nw[d + 1];
#pragma unroll
        for (int wi = 0; wi < 4; wi++)
            wnv2[wi][j] = pk(cw[d * 4 + wi] * n0, cw[(d + 1) * 4 + wi] * n1);
    }
#pragma unroll
    for (int c = 0; c < 4; c++) gch[c] = pw[DV + c0 + c] - pw[c0 + c];

    u64 acc2[4][2];
#pragma unroll
    for (int s = 0; s < 4; s++) { acc2[s][0] = 0ull; acc2[s][1] = 0ull; }

    // Chunks 0..4; ring base rotates 0,8,4,0,8 (compile-time).
    process_chunk<0, true , false>(0, s0, tid, lane, wid, ring, ring_u32,
                                   mbar_u32, xrow, acc2, wnv2, gch, rinv_s, pbuf);
    process_chunk<8, false, false>(1, s0, tid, lane, wid, ring, ring_u32,
                                   mbar_u32, xrow, acc2, wnv2, gch, rinv_s, pbuf);
    process_chunk<4, false, false>(2, s0, tid, lane, wid, ring, ring_u32,
                                   mbar_u32, xrow, acc2, wnv2, gch, rinv_s, pbuf);
    process_chunk<0, false, false>(3, s0, tid, lane, wid, ring, ring_u32,
                                   mbar_u32, xrow, acc2, wnv2, gch, rinv_s, pbuf);
    process_chunk<8, false, true >(4, s0, tid, lane, wid, ring, ring_u32,
                                   mbar_u32, xrow, acc2, wnv2, gch, rinv_s, pbuf);

    __syncthreads();
    if (tid < TOK) {
        const float4* sp = (const float4*)pbuf[tid];
        float t = 0.f;
#pragma unroll
        for (int j = 0; j < 16; j++) {
            const float4 v = sp[j];
            t += ((v.x + v.y) + (v.z + v.w));
        }
        g_mask[b * SV + s0 + tid] = (t > 0.f) ? 1 : 0;
    }
}

// K2: per-batch inclusive scan of masks -> inverse map src[b][c-1] = s -------
__global__ void __launch_bounds__(1024) scan_kernel() {
    const int b   = blockIdx.x;
    const int tid = threadIdx.x;
    for (int j = tid; j < SV; j += 1024) g_src[b * SV + j] = -1;
    __syncthreads();

    int base = tid * 4;
    int m[4], pre[4];
    int sum = 0;
#pragma unroll
    for (int k = 0; k < 4; k++) {
        m[k] = g_mask[b * SV + base + k];
        sum += m[k];
        pre[k] = sum;
    }
    int lane = tid & 31, wid = tid >> 5;
    int v = sum;
#pragma unroll
    for (int o = 1; o < 32; o <<= 1) {
        int t = __shfl_up_sync(0xffffffffu, v, o);
        if (lane >= o) v += t;
    }
    __shared__ int wsum[32];
    if (lane == 31) wsum[wid] = v;
    __syncthreads();
    if (wid == 0) {
        int t = wsum[lane];
#pragma unroll
        for (int o = 1; o < 32; o <<= 1) {
            int u = __shfl_up_sync(0xffffffffu, t, o);
            if (lane >= o) t += u;
        }
        wsum[lane] = t;
    }
    __syncthreads();
    int offset = (wid > 0 ? wsum[wid - 1] : 0) + (v - sum);
#pragma unroll
    for (int k = 0; k < 4; k++) {
        if (m[k]) g_src[b * SV + offset + pre[k] - 1] = base + k;
    }
}

// K3: row-wise gather of x (selected, packed) or zero-fill -------------------
__global__ void __launch_bounds__(256) scatter_kernel(
    const float* __restrict__ x, float* __restrict__ out)
{
    const int row = blockIdx.x;              // 0 .. B*S-1
    const int b   = row >> 12;               // S = 4096
    const int s   = g_src[row];
    float4* o = (float4*)(out + (size_t)row * DV) + threadIdx.x;
    if (s >= 0) {
        const float4* xr =
            (const float4*)(x + ((size_t)(b << 12) + s) * DV) + threadIdx.x;
        float4 v0 = __ldcs(xr);
        float4 v1 = __ldcs(xr + 256);
        __stcs(o, v0);
        __stcs(o + 256, v1);
    } else {
        float4 z = make_float4(0.f, 0.f, 0.f, 0.f);
        __stcs(o, z);
        __stcs(o + 256, z);
    }
}

extern "C" void kernel_launch(void* const* d_in, const int* in_sizes, int n_in,
                              void* d_out, int out_size) {
    const float* x  = (const float*)d_in[0];  // [B,S,D]
    const float* nw = (const float*)d_in[1];  // [D]
    const float* cw = (const float*)d_in[2];  // [D,4]
    const float* pw = (const float*)d_in[3];  // [2,D]
    float* out = (float*)d_out;               // [B,S,D]

    const int ring_bytes = 12 * 8192;         // 96KB dynamic smem
    cudaFuncSetAttribute(score_kernel,
                         cudaFuncAttributeMaxDynamicSharedMemorySize,
                         ring_bytes);
    cudaFuncSetAttribute(score_kernel,
                         cudaFuncAttributePreferredSharedMemoryCarveout, 100);

    dim3 g1(SV / TOK, BV);
    score_kernel<<<g1, THREADS, ring_bytes>>>(x, nw, cw, pw);
    scan_kernel<<<BV, 1024>>>();
    scatter_kernel<<<BV * SV, 256>>>(x, out);
}